// round 1
// baseline (speedup 1.0000x reference)
#include <cuda_runtime.h>
#include <math.h>

#define VOCAB 32000
#define DIM   300
#define B_    128
#define T_    512
#define H_    128
#define G3    384   // 3*H

// Scratch: per-direction projected embedding tables (b_i folded in).
// 2 * 32000 * 384 * 4B = 98.3 MB static device memory (allocation-free).
__device__ float g_proj[2][VOCAB * G3];

// ---------------------------------------------------------------------------
// Projection GEMM: proj[dir][v][g] = sum_k emb[v][k] * W[k][g] + b[0][g]
// BM=128, BN=64, BK=8, 256 threads, 8x4 register tile per thread.
// ---------------------------------------------------------------------------
__global__ __launch_bounds__(256)
void proj_kernel(const float* __restrict__ emb,
                 const float* __restrict__ W_f,
                 const float* __restrict__ b_f,
                 const float* __restrict__ W_b,
                 const float* __restrict__ b_b) {
    const int dir = blockIdx.z;
    const float* W  = dir ? W_b : W_f;
    const float* bi = dir ? b_b : b_f;   // row 0 = b_i
    const int vBase = blockIdx.x * 128;
    const int nBase = blockIdx.y * 64;

    __shared__ float As[8][132];   // padded (132) to kill STS bank conflicts
    __shared__ float Bs[8][64];

    const int tid = threadIdx.x;
    const int tx = tid & 15;       // 0..15  (N groups of 4)
    const int ty = tid >> 4;       // 0..15  (M groups of 8)

    float acc[8][4];
    #pragma unroll
    for (int i = 0; i < 8; i++)
        #pragma unroll
        for (int j = 0; j < 4; j++) acc[i][j] = 0.f;

    for (int kBase = 0; kBase < DIM; kBase += 8) {
        // Load A tile (128 rows x 8 k), store transposed As[k][m]
        {
            const int r  = tid >> 1;          // 0..127
            const int kk = (tid & 1) * 4;     // 0 or 4
            const float* ap = emb + (size_t)(vBase + r) * DIM + kBase + kk;
            #pragma unroll
            for (int j = 0; j < 4; j++) {
                const int k = kBase + kk + j;
                As[kk + j][r] = (k < DIM) ? ap[j] : 0.f;
            }
        }
        // Load B tile (8 k x 64 n)
        {
            const int idx = tid * 2;
            const int k = idx >> 6;           // 0..7
            const int n = idx & 63;           // even
            const bool ok = (kBase + k) < DIM;
            const float* bp = W + (size_t)(kBase + k) * G3 + nBase + n;
            Bs[k][n]     = ok ? bp[0] : 0.f;
            Bs[k][n + 1] = ok ? bp[1] : 0.f;
        }
        __syncthreads();

        #pragma unroll
        for (int k = 0; k < 8; k++) {
            float rm[8], rn[4];
            #pragma unroll
            for (int i = 0; i < 8; i++) rm[i] = As[k][ty * 8 + i];
            #pragma unroll
            for (int j = 0; j < 4; j++) rn[j] = Bs[k][tx * 4 + j];
            #pragma unroll
            for (int i = 0; i < 8; i++)
                #pragma unroll
                for (int j = 0; j < 4; j++)
                    acc[i][j] = fmaf(rm[i], rn[j], acc[i][j]);
        }
        __syncthreads();
    }

    float* outp = g_proj[dir];
    #pragma unroll
    for (int i = 0; i < 8; i++) {
        const int v = vBase + ty * 8 + i;
        #pragma unroll
        for (int j = 0; j < 4; j++) {
            const int n = nBase + tx * 4 + j;
            outp[(size_t)v * G3 + n] = acc[i][j] + bi[n];
        }
    }
}

// ---------------------------------------------------------------------------
// GRU scan kernel. One block = one direction x 2 batch rows, 384 threads.
// Thread g keeps U[:,g] (128 floats) in registers. h lives in SMEM and is
// broadcast-read. Per step: rec = h@U + b_r (FMA phase), then 256 threads do
// the gate math and write the output row.
// Grid: (64, 2) ; blockDim 384.
// ---------------------------------------------------------------------------
__global__ __launch_bounds__(384, 1)
void scan_kernel(const int*   __restrict__ enc,
                 const float* __restrict__ state_fwd,
                 const float* __restrict__ state_back,
                 const float* __restrict__ U_f,
                 const float* __restrict__ b_f,
                 const float* __restrict__ U_b,
                 const float* __restrict__ b_b,
                 float*       __restrict__ out) {
    const int dir = blockIdx.y;
    const int b0  = blockIdx.x * 2;
    const int g   = threadIdx.x;          // 0..383

    const float* U     = dir ? U_b : U_f;
    const float* br    = (dir ? b_b : b_f) + G3;   // row 1 = b_r
    const float* state = dir ? state_back : state_fwd;
    const float* proj  = g_proj[dir];

    __shared__ float h_sh[2 * H_];
    __shared__ float rec_sh[2 * G3];
    __shared__ float xp_sh[2][2 * G3];

    // Stage U column into registers
    float Ureg[128];
    #pragma unroll
    for (int i = 0; i < 128; i++) Ureg[i] = U[(size_t)i * G3 + g];
    const float brg = br[g];

    if (g < 256) {
        const int b = g >> 7, j = g & 127;
        h_sh[b * H_ + j] = state[(size_t)(b0 + b) * H_ + j];
    }
    // Preload xp for step 0
    {
        const int t0 = dir ? (T_ - 1) : 0;
        const int tok0 = enc[(size_t)(b0 + 0) * T_ + t0];
        const int tok1 = enc[(size_t)(b0 + 1) * T_ + t0];
        xp_sh[0][0 * G3 + g] = proj[(size_t)tok0 * G3 + g];
        xp_sh[0][1 * G3 + g] = proj[(size_t)tok1 * G3 + g];
    }
    __syncthreads();

    int cur = 0;
    for (int s = 0; s < T_; s++) {
        const int t = dir ? (T_ - 1 - s) : s;

        // Prefetch next step's xp rows (tokens are input-known)
        const int sn = (s + 1 < T_) ? (s + 1) : s;
        const int tn = dir ? (T_ - 1 - sn) : sn;
        const int tokn0 = enc[(size_t)(b0 + 0) * T_ + tn];
        const int tokn1 = enc[(size_t)(b0 + 1) * T_ + tn];
        const float xn0 = __ldg(&proj[(size_t)tokn0 * G3 + g]);
        const float xn1 = __ldg(&proj[(size_t)tokn1 * G3 + g]);

        // rec[b][g] = h[b] . U[:,g] + b_r[g]   (2 accum chains per batch)
        float a0 = brg, a1 = brg, c0 = 0.f, c1 = 0.f;
        #pragma unroll
        for (int i = 0; i < 128; i += 4) {
            const float4 ha = *reinterpret_cast<const float4*>(&h_sh[i]);
            const float4 hb = *reinterpret_cast<const float4*>(&h_sh[H_ + i]);
            a0 = fmaf(ha.x, Ureg[i],     a0);
            c0 = fmaf(ha.y, Ureg[i + 1], c0);
            a0 = fmaf(ha.z, Ureg[i + 2], a0);
            c0 = fmaf(ha.w, Ureg[i + 3], c0);
            a1 = fmaf(hb.x, Ureg[i],     a1);
            c1 = fmaf(hb.y, Ureg[i + 1], c1);
            a1 = fmaf(hb.z, Ureg[i + 2], a1);
            c1 = fmaf(hb.w, Ureg[i + 3], c1);
        }
        rec_sh[0 * G3 + g] = a0 + c0;
        rec_sh[1 * G3 + g] = a1 + c1;
        xp_sh[cur ^ 1][0 * G3 + g] = xn0;
        xp_sh[cur ^ 1][1 * G3 + g] = xn1;
        __syncthreads();

        if (g < 256) {
            const int b = g >> 7, j = g & 127;
            const float* rs = rec_sh + b * G3;
            const float* xs = xp_sh[cur] + b * G3;
            const float rz = rs[j], rr = rs[j + 128], rh = rs[j + 256];
            const float xz = xs[j], xr = xs[j + 128], xh = xs[j + 256];
            const float z = 1.f / (1.f + __expf(-(xz + rz)));
            const float r = 1.f / (1.f + __expf(-(xr + rr)));
            const float hh = tanhf(fmaf(r, rh, xh));
            const float hold = h_sh[b * H_ + j];
            const float hn = z * hold + (1.f - z) * hh;
            h_sh[b * H_ + j] = hn;
            out[(size_t)((b0 + b) * T_ + t) * (2 * H_) + dir * H_ + j] = hn;
        }
        __syncthreads();
        cur ^= 1;
    }

    // Final states: h_f then h_b after the (B,T,2H) block
    if (g < 256) {
        const int b = g >> 7, j = g & 127;
        out[(size_t)B_ * T_ * 2 * H_ + (size_t)dir * B_ * H_ +
            (size_t)(b0 + b) * H_ + j] = h_sh[b * H_ + j];
    }
}

// ---------------------------------------------------------------------------
// kernel_launch
// Inputs (metadata order):
//  0 encoder_input (int32, B*T)   1 state_fwd (B,H)   2 state_back (B,H)
//  3 emb (V,D)   4 W_f (D,3H)   5 U_f (H,3H)   6 b_f (2,3H)
//  7 W_b (D,3H)  8 U_b (H,3H)   9 b_b (2,3H)
// Output: [encoder_output (B,T,2H) | h_f (B,H) | h_b (B,H)] float32
// ---------------------------------------------------------------------------
extern "C" void kernel_launch(void* const* d_in, const int* in_sizes, int n_in,
                              void* d_out, int out_size) {
    const int*   enc   = (const int*)  d_in[0];
    const float* s_fwd = (const float*)d_in[1];
    const float* s_bck = (const float*)d_in[2];
    const float* emb   = (const float*)d_in[3];
    const float* W_f   = (const float*)d_in[4];
    const float* U_f   = (const float*)d_in[5];
    const float* b_f   = (const float*)d_in[6];
    const float* W_b   = (const float*)d_in[7];
    const float* U_b   = (const float*)d_in[8];
    const float* b_b   = (const float*)d_in[9];
    float* out = (float*)d_out;

    dim3 pgrid(VOCAB / 128, G3 / 64, 2);
    proj_kernel<<<pgrid, 256>>>(emb, W_f, b_f, W_b, b_b);

    dim3 sgrid(B_ / 2, 2);
    scan_kernel<<<sgrid, 384>>>(enc, s_fwd, s_bck, U_f, b_f, U_b, b_b, out);
}

// round 2
// speedup vs baseline: 1.0514x; 1.0514x over previous
#include <cuda_runtime.h>
#include <math.h>

#define VOCAB 32000
#define DIM   300
#define B_    128
#define T_    512
#define H_    128
#define G3    384   // 3*H

// Scratch: per-direction projected embedding tables (b_i folded in).
// 2 * 32000 * 384 * 4B = 98.3 MB static device memory (allocation-free).
__device__ float g_proj[2][VOCAB * G3];

// ---- packed f32x2 helpers (Blackwell sm_100+) -----------------------------
__device__ __forceinline__ unsigned long long ffma2(
    unsigned long long a, unsigned long long b, unsigned long long c) {
    unsigned long long d;
    asm("fma.rn.f32x2 %0, %1, %2, %3;" : "=l"(d) : "l"(a), "l"(b), "l"(c));
    return d;
}
__device__ __forceinline__ unsigned long long pack2(float lo, float hi) {
    unsigned long long r;
    asm("mov.b64 %0, {%1, %2};" : "=l"(r) : "f"(lo), "f"(hi));
    return r;
}
__device__ __forceinline__ float2 unpack2(unsigned long long v) {
    float lo, hi;
    asm("mov.b64 {%0, %1}, %2;" : "=f"(lo), "=f"(hi) : "l"(v));
    return make_float2(lo, hi);
}
__device__ __forceinline__ unsigned long long d_as_ull(double d) {
    return __double_as_longlong(d);
}

// ---------------------------------------------------------------------------
// Projection GEMM: proj[dir][v][g] = sum_k emb[v][k] * W[k][g] + b[0][g]
// BM=128, BN=128, BK=8, 256 threads, 8x8 register tile, f32x2 accumulation
// packed along N (n-pairs come straight out of Bs as 64-bit LDS).
// ---------------------------------------------------------------------------
__global__ __launch_bounds__(256, 2)
void proj_kernel(const float* __restrict__ emb,
                 const float* __restrict__ W_f,
                 const float* __restrict__ b_f,
                 const float* __restrict__ W_b,
                 const float* __restrict__ b_b) {
    const int dir = blockIdx.z;
    const float* W  = dir ? W_b : W_f;
    const float* bi = dir ? b_b : b_f;   // row 0 = b_i
    const int vBase = blockIdx.x * 128;
    const int nBase = blockIdx.y * 128;

    __shared__ float As[8][132];                   // padded
    __shared__ __align__(16) float Bs[8][128];

    const int tid = threadIdx.x;
    const int tx = tid & 15;       // 0..15  (N groups of 8)
    const int ty = tid >> 4;       // 0..15  (M groups of 8)

    unsigned long long acc[8][4];  // 8 m-rows x 4 n-pairs
    #pragma unroll
    for (int i = 0; i < 8; i++)
        #pragma unroll
        for (int j = 0; j < 4; j++) acc[i][j] = 0ull;

    for (int kBase = 0; kBase < DIM; kBase += 8) {
        // Load A tile (128 rows x 8 k), store transposed As[k][m]
        {
            const int r  = tid >> 1;          // 0..127
            const int kk = (tid & 1) * 4;     // 0 or 4
            const float* ap = emb + (size_t)(vBase + r) * DIM + kBase + kk;
            if (kBase + kk + 3 < DIM) {
                const float4 v = *reinterpret_cast<const float4*>(ap);
                As[kk + 0][r] = v.x; As[kk + 1][r] = v.y;
                As[kk + 2][r] = v.z; As[kk + 3][r] = v.w;
            } else {
                #pragma unroll
                for (int j = 0; j < 4; j++)
                    As[kk + j][r] = (kBase + kk + j < DIM) ? ap[j] : 0.f;
            }
        }
        // Load B tile (8 k x 128 n), float4 per thread
        {
            const int k = tid >> 5;           // 0..7
            const int n = (tid & 31) * 4;     // 0..124
            if (kBase + k < DIM) {
                const float4 v = *reinterpret_cast<const float4*>(
                    W + (size_t)(kBase + k) * G3 + nBase + n);
                *reinterpret_cast<float4*>(&Bs[k][n]) = v;
            } else {
                *reinterpret_cast<float4*>(&Bs[k][n]) =
                    make_float4(0.f, 0.f, 0.f, 0.f);
            }
        }
        __syncthreads();

        #pragma unroll
        for (int k = 0; k < 8; k++) {
            // duplicate each rm into a packed pair (ALU pipe, idle otherwise)
            unsigned long long rmd[8];
            #pragma unroll
            for (int i = 0; i < 8; i++) {
                const float m = As[k][ty * 8 + i];
                rmd[i] = pack2(m, m);
            }
            const double2 n01 = *reinterpret_cast<const double2*>(&Bs[k][tx * 8]);
            const double2 n23 = *reinterpret_cast<const double2*>(&Bs[k][tx * 8 + 4]);
            unsigned long long rn[4] = { d_as_ull(n01.x), d_as_ull(n01.y),
                                         d_as_ull(n23.x), d_as_ull(n23.y) };
            #pragma unroll
            for (int i = 0; i < 8; i++)
                #pragma unroll
                for (int j = 0; j < 4; j++)
                    acc[i][j] = ffma2(rmd[i], rn[j], acc[i][j]);
        }
        __syncthreads();
    }

    float* outp = g_proj[dir];
    #pragma unroll
    for (int i = 0; i < 8; i++) {
        const int v = vBase + ty * 8 + i;
        float* orow = outp + (size_t)v * G3 + nBase + tx * 8;
        #pragma unroll
        for (int j = 0; j < 4; j++) {
            const float2 r = unpack2(acc[i][j]);
            const int n = nBase + tx * 8 + j * 2;
            orow[j * 2]     = r.x + bi[n];
            orow[j * 2 + 1] = r.y + bi[n + 1];
        }
    }
}

// ---------------------------------------------------------------------------
// GRU scan kernel. One block = one direction x 2 batch rows, 384 threads.
// Thread g keeps U[:,g] packed as 64 f32x2 K-pairs in registers. h lives in
// SMEM; LDS.128 of h yields two packed K-pairs directly (no repacking).
// rec = h @ U + b_r runs entirely on fma.rn.f32x2: 128 FMA-issues/thread/step.
// Grid: (64, 2) ; blockDim 384.
// ---------------------------------------------------------------------------
__global__ __launch_bounds__(384, 1)
void scan_kernel(const int*   __restrict__ enc,
                 const float* __restrict__ state_fwd,
                 const float* __restrict__ state_back,
                 const float* __restrict__ U_f,
                 const float* __restrict__ b_f,
                 const float* __restrict__ U_b,
                 const float* __restrict__ b_b,
                 float*       __restrict__ out) {
    const int dir = blockIdx.y;
    const int b0  = blockIdx.x * 2;
    const int g   = threadIdx.x;          // 0..383

    const float* U     = dir ? U_b : U_f;
    const float* br    = (dir ? b_b : b_f) + G3;   // row 1 = b_r
    const float* state = dir ? state_back : state_fwd;
    const float* proj  = g_proj[dir];

    __shared__ __align__(16) float h_sh[2 * H_];
    __shared__ float rec_sh[2 * G3];
    __shared__ float xp_sh[2][2 * G3];

    // Stage U column into registers as packed K-pairs (U[2i][g], U[2i+1][g])
    unsigned long long Up[64];
    #pragma unroll
    for (int i = 0; i < 64; i++)
        Up[i] = pack2(U[(size_t)(2 * i) * G3 + g],
                      U[(size_t)(2 * i + 1) * G3 + g]);
    const float brg = br[g];

    if (g < 256) {
        const int b = g >> 7, j = g & 127;
        h_sh[b * H_ + j] = state[(size_t)(b0 + b) * H_ + j];
    }
    // Preload xp for step 0
    {
        const int t0 = dir ? (T_ - 1) : 0;
        const int tok0 = enc[(size_t)(b0 + 0) * T_ + t0];
        const int tok1 = enc[(size_t)(b0 + 1) * T_ + t0];
        xp_sh[0][0 * G3 + g] = proj[(size_t)tok0 * G3 + g];
        xp_sh[0][1 * G3 + g] = proj[(size_t)tok1 * G3 + g];
    }
    __syncthreads();

    int cur = 0;
    for (int s = 0; s < T_; s++) {
        const int t = dir ? (T_ - 1 - s) : s;

        // Prefetch next step's xp rows (tokens are input-known)
        const int sn = (s + 1 < T_) ? (s + 1) : s;
        const int tn = dir ? (T_ - 1 - sn) : sn;
        const int tokn0 = enc[(size_t)(b0 + 0) * T_ + tn];
        const int tokn1 = enc[(size_t)(b0 + 1) * T_ + tn];
        const float xn0 = __ldg(&proj[(size_t)tokn0 * G3 + g]);
        const float xn1 = __ldg(&proj[(size_t)tokn1 * G3 + g]);

        // rec[b][g] = h[b] . U[:,g] + b_r[g]  via packed f32x2
        unsigned long long a0 = 0ull, a1 = 0ull;  // batch 0, 2 chains
        unsigned long long a2 = 0ull, a3 = 0ull;  // batch 1, 2 chains
        const double2* h0p = reinterpret_cast<const double2*>(h_sh);
        const double2* h1p = reinterpret_cast<const double2*>(h_sh + H_);
        #pragma unroll
        for (int j = 0; j < 32; j++) {
            const double2 da = h0p[j];   // packed pairs (h[4j],h[4j+1]) (h[4j+2],h[4j+3])
            const double2 db = h1p[j];
            a0 = ffma2(d_as_ull(da.x), Up[2 * j],     a0);
            a1 = ffma2(d_as_ull(da.y), Up[2 * j + 1], a1);
            a2 = ffma2(d_as_ull(db.x), Up[2 * j],     a2);
            a3 = ffma2(d_as_ull(db.y), Up[2 * j + 1], a3);
        }
        const float2 r0 = unpack2(a0), r1 = unpack2(a1);
        const float2 r2 = unpack2(a2), r3 = unpack2(a3);
        rec_sh[0 * G3 + g] = brg + ((r0.x + r0.y) + (r1.x + r1.y));
        rec_sh[1 * G3 + g] = brg + ((r2.x + r2.y) + (r3.x + r3.y));
        xp_sh[cur ^ 1][0 * G3 + g] = xn0;
        xp_sh[cur ^ 1][1 * G3 + g] = xn1;
        __syncthreads();

        if (g < 256) {
            const int b = g >> 7, j = g & 127;
            const float* rs = rec_sh + b * G3;
            const float* xs = xp_sh[cur] + b * G3;
            const float rz = rs[j], rr = rs[j + 128], rh = rs[j + 256];
            const float xz = xs[j], xr = xs[j + 128], xh = xs[j + 256];
            const float z = 1.f / (1.f + __expf(-(xz + rz)));
            const float r = 1.f / (1.f + __expf(-(xr + rr)));
            const float hh = tanhf(fmaf(r, rh, xh));
            const float hold = h_sh[b * H_ + j];
            const float hn = z * hold + (1.f - z) * hh;
            h_sh[b * H_ + j] = hn;
            out[(size_t)((b0 + b) * T_ + t) * (2 * H_) + dir * H_ + j] = hn;
        }
        __syncthreads();
        cur ^= 1;
    }

    // Final states: h_f then h_b after the (B,T,2H) block
    if (g < 256) {
        const int b = g >> 7, j = g & 127;
        out[(size_t)B_ * T_ * 2 * H_ + (size_t)dir * B_ * H_ +
            (size_t)(b0 + b) * H_ + j] = h_sh[b * H_ + j];
    }
}

// ---------------------------------------------------------------------------
// kernel_launch
// Inputs (metadata order):
//  0 encoder_input (int32, B*T)   1 state_fwd (B,H)   2 state_back (B,H)
//  3 emb (V,D)   4 W_f (D,3H)   5 U_f (H,3H)   6 b_f (2,3H)
//  7 W_b (D,3H)  8 U_b (H,3H)   9 b_b (2,3H)
// Output: [encoder_output (B,T,2H) | h_f (B,H) | h_b (B,H)] float32
// ---------------------------------------------------------------------------
extern "C" void kernel_launch(void* const* d_in, const int* in_sizes, int n_in,
                              void* d_out, int out_size) {
    const int*   enc   = (const int*)  d_in[0];
    const float* s_fwd = (const float*)d_in[1];
    const float* s_bck = (const float*)d_in[2];
    const float* emb   = (const float*)d_in[3];
    const float* W_f   = (const float*)d_in[4];
    const float* U_f   = (const float*)d_in[5];
    const float* b_f   = (const float*)d_in[6];
    const float* W_b   = (const float*)d_in[7];
    const float* U_b   = (const float*)d_in[8];
    const float* b_b   = (const float*)d_in[9];
    float* out = (float*)d_out;

    dim3 pgrid(VOCAB / 128, G3 / 128, 2);
    proj_kernel<<<pgrid, 256>>>(emb, W_f, b_f, W_b, b_b);

    dim3 sgrid(B_ / 2, 2);
    scan_kernel<<<sgrid, 384>>>(enc, s_fwd, s_bck, U_f, b_f, U_b, b_b, out);
}

// round 3
// speedup vs baseline: 1.1937x; 1.1353x over previous
#include <cuda_runtime.h>
#include <math.h>

#define VOCAB 32000
#define DIM   300
#define B_    128
#define T_    512
#define H_    128
#define G3    384   // 3*H

// Scratch: per-direction projected embedding tables (b_i folded in).
// 2 * 32000 * 384 * 4B = 98.3 MB static device memory (allocation-free).
__device__ float g_proj[2][VOCAB * G3];

// ---- packed f32x2 helpers (Blackwell sm_100+) -----------------------------
__device__ __forceinline__ unsigned long long ffma2(
    unsigned long long a, unsigned long long b, unsigned long long c) {
    unsigned long long d;
    asm("fma.rn.f32x2 %0, %1, %2, %3;" : "=l"(d) : "l"(a), "l"(b), "l"(c));
    return d;
}
__device__ __forceinline__ unsigned long long pack2(float lo, float hi) {
    unsigned long long r;
    asm("mov.b64 %0, {%1, %2};" : "=l"(r) : "f"(lo), "f"(hi));
    return r;
}
__device__ __forceinline__ float2 unpack2(unsigned long long v) {
    float lo, hi;
    asm("mov.b64 {%0, %1}, %2;" : "=f"(lo), "=f"(hi) : "l"(v));
    return make_float2(lo, hi);
}
__device__ __forceinline__ unsigned long long d_as_ull(double d) {
    return __double_as_longlong(d);
}
// fast sigmoid: 1/(1+e^-x) via MUFU (EX2 + RCP), branch-free, sat-safe
__device__ __forceinline__ float fsigmoid(float x) {
    const float e = __expf(-x);
    return __fdividef(1.f, 1.f + e);
}
// fast tanh: 2*sigmoid(2y) - 1, NaN-safe at both saturation ends
__device__ __forceinline__ float ftanh(float y) {
    const float e = __expf(-2.f * y);
    const float s = __fdividef(1.f, 1.f + e);
    return fmaf(2.f, s, -1.f);
}

// ---------------------------------------------------------------------------
// Projection GEMM: proj[dir][v][g] = sum_k emb[v][k] * W[k][g] + b[0][g]
// BM=128, BN=128, BK=8, 256 threads, 8x8 register tile, f32x2 accumulation.
// ---------------------------------------------------------------------------
__global__ __launch_bounds__(256, 2)
void proj_kernel(const float* __restrict__ emb,
                 const float* __restrict__ W_f,
                 const float* __restrict__ b_f,
                 const float* __restrict__ W_b,
                 const float* __restrict__ b_b) {
    const int dir = blockIdx.z;
    const float* W  = dir ? W_b : W_f;
    const float* bi = dir ? b_b : b_f;   // row 0 = b_i
    const int vBase = blockIdx.x * 128;
    const int nBase = blockIdx.y * 128;

    __shared__ float As[8][132];                   // padded
    __shared__ __align__(16) float Bs[8][128];

    const int tid = threadIdx.x;
    const int tx = tid & 15;       // 0..15  (N groups of 8)
    const int ty = tid >> 4;       // 0..15  (M groups of 8)

    unsigned long long acc[8][4];  // 8 m-rows x 4 n-pairs
    #pragma unroll
    for (int i = 0; i < 8; i++)
        #pragma unroll
        for (int j = 0; j < 4; j++) acc[i][j] = 0ull;

    for (int kBase = 0; kBase < DIM; kBase += 8) {
        // Load A tile (128 rows x 8 k), store transposed As[k][m]
        {
            const int r  = tid >> 1;          // 0..127
            const int kk = (tid & 1) * 4;     // 0 or 4
            const float* ap = emb + (size_t)(vBase + r) * DIM + kBase + kk;
            if (kBase + kk + 3 < DIM) {
                const float4 v = *reinterpret_cast<const float4*>(ap);
                As[kk + 0][r] = v.x; As[kk + 1][r] = v.y;
                As[kk + 2][r] = v.z; As[kk + 3][r] = v.w;
            } else {
                #pragma unroll
                for (int j = 0; j < 4; j++)
                    As[kk + j][r] = (kBase + kk + j < DIM) ? ap[j] : 0.f;
            }
        }
        // Load B tile (8 k x 128 n), float4 per thread
        {
            const int k = tid >> 5;           // 0..7
            const int n = (tid & 31) * 4;     // 0..124
            if (kBase + k < DIM) {
                const float4 v = *reinterpret_cast<const float4*>(
                    W + (size_t)(kBase + k) * G3 + nBase + n);
                *reinterpret_cast<float4*>(&Bs[k][n]) = v;
            } else {
                *reinterpret_cast<float4*>(&Bs[k][n]) =
                    make_float4(0.f, 0.f, 0.f, 0.f);
            }
        }
        __syncthreads();

        #pragma unroll
        for (int k = 0; k < 8; k++) {
            unsigned long long rmd[8];
            #pragma unroll
            for (int i = 0; i < 8; i++) {
                const float m = As[k][ty * 8 + i];
                rmd[i] = pack2(m, m);
            }
            const double2 n01 = *reinterpret_cast<const double2*>(&Bs[k][tx * 8]);
            const double2 n23 = *reinterpret_cast<const double2*>(&Bs[k][tx * 8 + 4]);
            unsigned long long rn[4] = { d_as_ull(n01.x), d_as_ull(n01.y),
                                         d_as_ull(n23.x), d_as_ull(n23.y) };
            #pragma unroll
            for (int i = 0; i < 8; i++)
                #pragma unroll
                for (int j = 0; j < 4; j++)
                    acc[i][j] = ffma2(rmd[i], rn[j], acc[i][j]);
        }
        __syncthreads();
    }

    float* outp = g_proj[dir];
    #pragma unroll
    for (int i = 0; i < 8; i++) {
        const int v = vBase + ty * 8 + i;
        float* orow = outp + (size_t)v * G3 + nBase + tx * 8;
        #pragma unroll
        for (int j = 0; j < 4; j++) {
            const float2 r = unpack2(acc[i][j]);
            const int n = nBase + tx * 8 + j * 2;
            orow[j * 2]     = r.x + bi[n];
            orow[j * 2 + 1] = r.y + bi[n + 1];
        }
    }
}

// ---------------------------------------------------------------------------
// GRU scan kernel. One block = one direction x 2 batch rows, 384 threads.
// Thread g keeps U[:,g] packed as 64 f32x2 K-pairs in registers.
// Tokens are preloaded to SMEM (kills the enc->proj serial LDG chain).
// proj-row gathers are prefetched 2 steps ahead (register double-buffer,
// flushed to SMEM during the gate phase) -> DRAM latency fully hidden.
// Grid: (64, 2) ; blockDim 384.
// ---------------------------------------------------------------------------
__global__ __launch_bounds__(384, 1)
void scan_kernel(const int*   __restrict__ enc,
                 const float* __restrict__ state_fwd,
                 const float* __restrict__ state_back,
                 const float* __restrict__ U_f,
                 const float* __restrict__ b_f,
                 const float* __restrict__ U_b,
                 const float* __restrict__ b_b,
                 float*       __restrict__ out) {
    const int dir = blockIdx.y;
    const int b0  = blockIdx.x * 2;
    const int g   = threadIdx.x;          // 0..383

    const float* U     = dir ? U_b : U_f;
    const float* br    = (dir ? b_b : b_f) + G3;   // row 1 = b_r
    const float* state = dir ? state_back : state_fwd;
    const float* proj  = g_proj[dir];

    __shared__ __align__(16) float h_sh[2 * H_];
    __shared__ float rec_sh[2 * G3];
    __shared__ float xp_sh[2][2 * G3];
    __shared__ int   tok_sh[2][T_];

    // Stage U column into registers as packed K-pairs (U[2i][g], U[2i+1][g])
    unsigned long long Up[64];
    #pragma unroll
    for (int i = 0; i < 64; i++)
        Up[i] = pack2(U[(size_t)(2 * i) * G3 + g],
                      U[(size_t)(2 * i + 1) * G3 + g]);
    const float brg = br[g];

    // Preload all tokens for both batch rows (4 KB)
    for (int i = g; i < 2 * T_; i += 384) {
        const int b = i >> 9, t = i & (T_ - 1);
        tok_sh[b][t] = enc[(size_t)(b0 + b) * T_ + t];
    }

    if (g < 256) {
        const int b = g >> 7, j = g & 127;
        h_sh[b * H_ + j] = state[(size_t)(b0 + b) * H_ + j];
    }

    // Pre-loop: xp for s=0 straight into smem; xp for s=1 into reg buffer[1]
    float bufA[2], bufB[2];
    {
        const int t0 = dir ? (T_ - 1) : 0;
        const int t1 = dir ? (T_ - 2) : 1;
        xp_sh[0][0 * G3 + g] = proj[(size_t)enc[(size_t)b0 * T_ + t0] * G3 + g];
        xp_sh[0][1 * G3 + g] = proj[(size_t)enc[(size_t)(b0 + 1) * T_ + t0] * G3 + g];
        bufA[1] = __ldg(&proj[(size_t)enc[(size_t)b0 * T_ + t1] * G3 + g]);
        bufB[1] = __ldg(&proj[(size_t)enc[(size_t)(b0 + 1) * T_ + t1] * G3 + g]);
        bufA[0] = 0.f; bufB[0] = 0.f;
    }
    __syncthreads();

    int cur = 0;
    #pragma unroll 2
    for (int s = 0; s < T_; s++) {
        const int t = dir ? (T_ - 1 - s) : s;

        // Issue LDG for step s+2 into buffer[s&1] (tokens come from SMEM)
        const int s2 = (s + 2 < T_) ? (s + 2) : (T_ - 1);
        const int t2 = dir ? (T_ - 1 - s2) : s2;
        const float fa = __ldg(&proj[(size_t)tok_sh[0][t2] * G3 + g]);
        const float fb = __ldg(&proj[(size_t)tok_sh[1][t2] * G3 + g]);

        // rec[b][g] = h[b] . U[:,g] + b_r[g]  via packed f32x2
        unsigned long long a0 = 0ull, a1 = 0ull;  // batch 0
        unsigned long long a2 = 0ull, a3 = 0ull;  // batch 1
        const double2* h0p = reinterpret_cast<const double2*>(h_sh);
        const double2* h1p = reinterpret_cast<const double2*>(h_sh + H_);
        #pragma unroll
        for (int j = 0; j < 32; j++) {
            const double2 da = h0p[j];
            const double2 db = h1p[j];
            a0 = ffma2(d_as_ull(da.x), Up[2 * j],     a0);
            a1 = ffma2(d_as_ull(da.y), Up[2 * j + 1], a1);
            a2 = ffma2(d_as_ull(db.x), Up[2 * j],     a2);
            a3 = ffma2(d_as_ull(db.y), Up[2 * j + 1], a3);
        }
        const float2 r0 = unpack2(a0), r1 = unpack2(a1);
        const float2 r2 = unpack2(a2), r3 = unpack2(a3);
        rec_sh[0 * G3 + g] = brg + ((r0.x + r0.y) + (r1.x + r1.y));
        rec_sh[1 * G3 + g] = brg + ((r2.x + r2.y) + (r3.x + r3.y));
        __syncthreads();   // bar1: rec ready

        // Flush pending xp (step s+1, issued at step s-1 -> long since arrived)
        xp_sh[cur ^ 1][0 * G3 + g] = bufA[(s + 1) & 1];
        xp_sh[cur ^ 1][1 * G3 + g] = bufB[(s + 1) & 1];

        if (g < 256) {
            const int b = g >> 7, j = g & 127;
            const float* rs = rec_sh + b * G3;
            const float* xs = xp_sh[cur] + b * G3;
            const float rz = rs[j], rr = rs[j + 128], rh = rs[j + 256];
            const float xz = xs[j], xr = xs[j + 128], xh = xs[j + 256];
            const float z = fsigmoid(xz + rz);
            const float r = fsigmoid(xr + rr);
            const float hh = ftanh(fmaf(r, rh, xh));
            const float hold = h_sh[b * H_ + j];
            const float hn = z * hold + (1.f - z) * hh;
            h_sh[b * H_ + j] = hn;
            out[(size_t)((b0 + b) * T_ + t) * (2 * H_) + dir * H_ + j] = hn;
        }
        __syncthreads();   // bar2: h & xp ready for next step

        bufA[s & 1] = fa;
        bufB[s & 1] = fb;
        cur ^= 1;
    }

    // Final states: h_f then h_b after the (B,T,2H) block
    if (g < 256) {
        const int b = g >> 7, j = g & 127;
        out[(size_t)B_ * T_ * 2 * H_ + (size_t)dir * B_ * H_ +
            (size_t)(b0 + b) * H_ + j] = h_sh[b * H_ + j];
    }
}

// ---------------------------------------------------------------------------
// kernel_launch
// ---------------------------------------------------------------------------
extern "C" void kernel_launch(void* const* d_in, const int* in_sizes, int n_in,
                              void* d_out, int out_size) {
    const int*   enc   = (const int*)  d_in[0];
    const float* s_fwd = (const float*)d_in[1];
    const float* s_bck = (const float*)d_in[2];
    const float* emb   = (const float*)d_in[3];
    const float* W_f   = (const float*)d_in[4];
    const float* U_f   = (const float*)d_in[5];
    const float* b_f   = (const float*)d_in[6];
    const float* W_b   = (const float*)d_in[7];
    const float* U_b   = (const float*)d_in[8];
    const float* b_b   = (const float*)d_in[9];
    float* out = (float*)d_out;

    dim3 pgrid(VOCAB / 128, G3 / 128, 2);
    proj_kernel<<<pgrid, 256>>>(emb, W_f, b_f, W_b, b_b);

    dim3 sgrid(B_ / 2, 2);
    scan_kernel<<<sgrid, 384>>>(enc, s_fwd, s_bck, U_f, b_f, U_b, b_b, out);
}